// round 17
// baseline (speedup 1.0000x reference)
#include <cuda_runtime.h>
#include <cstdint>

// ---------------------------------------------------------------------------
// sincKAN: layers 0/1 = frozen fp32 FFMA GEMM (R12, at FFMA roofline);
// layer 2 (output, amplification factor 1) = bf16x6 tensor-core GEMM.
//   fp32 v = hi+mid+lo (exact bf16 triple); 6 exact products accumulated in
//   fp32 via mma.sync.m16n8k16.bf16. Measured mma-path noise ~1.4e-4/layer
//   is un-amplified at the last layer -> total ~8.3e-4 predicted.
// A^T[klin][b] fp32 (shared by both GEMM types; split in-register for mma).
// W: fp32 [K][O] for layers 0/1; 3 packed bf16x2 planes [K/2][O] for layer 2.
// Split-K=8 with deterministic fp32 reduction (+beta) everywhere.
// ---------------------------------------------------------------------------

#define BATCH   1024
#define SPLITS  8
#define BM      128
#define BN      128
#define BK      16

// Static device scratch (~537 MB; allocation APIs banned)
__device__ float    g_x0[BATCH * 256];
__device__ float    g_x1[BATCH * 512];
__device__ float    g_x2[BATCH * 512];
__device__ float    g_A [(size_t)131 * 512 * BATCH];    // A^T fp32 [K][1024]
__device__ float    g_W [(size_t)131 * 512 * 512];      // fp32 W, layers 0/1
__device__ uint32_t g_WH[(size_t)131 * 256 * 256];      // layer-2 planes [K/2][256]
__device__ uint32_t g_WM[(size_t)131 * 256 * 256];
__device__ uint32_t g_WL[(size_t)131 * 256 * 256];
__device__ float    g_P [(size_t)SPLITS * BATCH * 512]; // split-K partials

// ---------------------------------------------------------------------------
__device__ __forceinline__ void split_pack(float v0, float v1,
                                           uint32_t& h, uint32_t& m, uint32_t& l) {
    uint32_t hp, mp, lp;
    asm("cvt.rn.bf16x2.f32 %0, %1, %2;" : "=r"(hp) : "f"(v1), "f"(v0));
    float h0 = __uint_as_float(hp << 16);
    float h1 = __uint_as_float(hp & 0xFFFF0000u);
    float r0 = v0 - h0, r1 = v1 - h1;
    asm("cvt.rn.bf16x2.f32 %0, %1, %2;" : "=r"(mp) : "f"(r1), "f"(r0));
    float m0 = __uint_as_float(mp << 16);
    float m1 = __uint_as_float(mp & 0xFFFF0000u);
    float s0 = r0 - m0, s1 = r1 - m1;
    asm("cvt.rn.bf16x2.f32 %0, %1, %2;" : "=r"(lp) : "f"(s1), "f"(s0));
    h = hp; m = mp; l = lp;
}

__device__ __forceinline__ void cp16(void* smem_dst, const void* gmem_src) {
    uint32_t s = (uint32_t)__cvta_generic_to_shared(smem_dst);
    asm volatile("cp.async.cg.shared.global [%0], [%1], 16;\n" :: "r"(s), "l"(gmem_src));
}

__device__ __forceinline__ void mma_bf16(float* c, const uint32_t* a, const uint32_t* b) {
    asm volatile(
        "mma.sync.aligned.m16n8k16.row.col.f32.bf16.bf16.f32 "
        "{%0,%1,%2,%3}, {%4,%5,%6,%7}, {%8,%9}, {%0,%1,%2,%3};\n"
        : "+f"(c[0]), "+f"(c[1]), "+f"(c[2]), "+f"(c[3])
        : "r"(a[0]), "r"(a[1]), "r"(a[2]), "r"(a[3]), "r"(b[0]), "r"(b[1]));
}

// ---------------------------------------------------------------------------
__global__ void tanh_kernel(const float* __restrict__ in, float* __restrict__ out, int n) {
    int t = blockIdx.x * blockDim.x + threadIdx.x;
    if (t < n) out[t] = tanhf(in[t]);
}

// ---------------------------------------------------------------------------
// A generation into A^T[klin][b] (fp32) — unchanged from passing kernels.
// ---------------------------------------------------------------------------
__global__ void agen_kernel(const float* __restrict__ X, int I) {
    const int t = blockIdx.x * blockDim.x + threadIdx.x;
    const int b = t & (BATCH - 1);
    const int i = t >> 10;

    const float x = X[(size_t)b * I + i];
    g_A[(size_t)i * BATCH + b] = x;                    // skip row j=0

    const float xa = tanhf(x);
    const float INV_PI = 0.31830988618379067f;
    const size_t stride = (size_t)I * BATCH;

    #pragma unroll
    for (int kh = 0; kh < 2; kh++) {
        const float tt = xa * (kh ? 8.0f : 4.0f);
        const float sp = sinpif(tt) * INV_PI;
        float* dst = g_A + ((size_t)(1 + kh * 65) * I + i) * BATCH + b;

        int d = 0;
        #pragma unroll
        for (int g = 0; g < 8; g++) {
            float e[8], p[8], inv[8];
            bool  z[8];
            #pragma unroll
            for (int j = 0; j < 8; j++) {
                float ee = tt + (float)(d + j - 32);
                z[j] = (ee == 0.0f);
                e[j] = z[j] ? 1.0f : ee;
            }
            p[0] = e[0];
            #pragma unroll
            for (int j = 1; j < 8; j++) p[j] = p[j - 1] * e[j];
            float r = __frcp_rn(p[7]);
            #pragma unroll
            for (int j = 7; j >= 1; j--) { inv[j] = r * p[j - 1]; r *= e[j]; }
            inv[0] = r;
            #pragma unroll
            for (int j = 0; j < 8; j++) {
                int dd = d + j;
                float sgn = (dd & 1) ? -sp : sp;
                dst[(size_t)dd * stride] = z[j] ? 1.0f : sgn * inv[j];
            }
            d += 8;
        }
        {
            float ee = tt + 32.0f;
            dst[(size_t)64 * stride] = (ee == 0.0f) ? 1.0f : sp * __frcp_rn(ee);
        }
    }
}

// ---------------------------------------------------------------------------
// W generation (fp32), layers 0/1 — unchanged.
// ---------------------------------------------------------------------------
__global__ void wgen_kernel(const float* __restrict__ C, const float* __restrict__ alpha,
                            int I, int O) {
    const int i  = blockIdx.x;
    const int o0 = blockIdx.y * 64;
    __shared__ float sm[130][65];

    const float* Ci = C + ((size_t)i * O + o0) * 130;
    for (int idx = threadIdx.x; idx < 64 * 130; idx += blockDim.x) {
        int ol = idx / 130, m = idx - ol * 130;
        sm[m][ol] = Ci[(size_t)ol * 130 + m];
    }
    __syncthreads();

    for (int ol = threadIdx.x; ol < 64; ol += blockDim.x)
        g_W[(size_t)i * O + o0 + ol] = alpha[(size_t)i * O + o0 + ol];

    for (int idx = threadIdx.x; idx < 64 * 130; idx += blockDim.x) {
        int m = idx >> 6, ol = idx & 63;
        g_W[((size_t)(1 + m) * I + i) * O + o0 + ol] = sm[m][ol];
    }
}

// ---------------------------------------------------------------------------
// W generation into packed bf16x2 planes (layer 2). k-pairs = (i even, i odd)
// within same j. Plane row = klin/2 = j*(I/2)+i2.
// ---------------------------------------------------------------------------
__global__ void wgen_mma_kernel(const float* __restrict__ C, const float* __restrict__ alpha,
                                int I, int O) {
    const int i2 = blockIdx.x;
    const int i0 = i2 * 2;
    const int o0 = blockIdx.y * 32;
    __shared__ float sm[2][130][33];

    #pragma unroll
    for (int ii = 0; ii < 2; ii++) {
        const float* Ci = C + ((size_t)(i0 + ii) * O + o0) * 130;
        for (int idx = threadIdx.x; idx < 32 * 130; idx += blockDim.x) {
            int ol = idx / 130, m = idx - ol * 130;
            sm[ii][m][ol] = Ci[(size_t)ol * 130 + m];
        }
    }
    __syncthreads();

    for (int ol = threadIdx.x; ol < 32; ol += blockDim.x) {
        float v0 = alpha[(size_t)i0 * O + o0 + ol];
        float v1 = alpha[(size_t)(i0 + 1) * O + o0 + ol];
        size_t w = (size_t)i2 * O + o0 + ol;
        uint32_t h, m, l;
        split_pack(v0, v1, h, m, l);
        g_WH[w] = h; g_WM[w] = m; g_WL[w] = l;
    }
    for (int idx = threadIdx.x; idx < 32 * 130; idx += blockDim.x) {
        int m = idx >> 5, ol = idx & 31;
        size_t w = ((size_t)(1 + m) * (I / 2) + i2) * O + o0 + ol;
        uint32_t hh, mm, ll;
        split_pack(sm[0][m][ol], sm[1][m][ol], hh, mm, ll);
        g_WH[w] = hh; g_WM[w] = mm; g_WL[w] = ll;
    }
}

// ---------------------------------------------------------------------------
// FROZEN R12 pure-FP32 SGEMM (layers 0/1): 8x8 micro-tile, BK=16, split-K=8,
// two-level accumulation, double-buffered cp.async.
// ---------------------------------------------------------------------------
__global__ void __launch_bounds__(256, 1)
gemm_kernel(int K, int N) {
    __shared__ float As[2][BK][BM + 4];
    __shared__ float Ws[2][BK][BN + 4];

    const int tid = threadIdx.x;
    const int tx  = tid & 15;
    const int ty  = tid >> 4;

    const int nBase  = blockIdx.x * BN;
    const int mBase  = blockIdx.y * BM;
    const int Kper   = K / SPLITS;
    const int kSplit = blockIdx.z * Kper;
    const int ntiles = Kper / BK;

    auto loadTiles = [&](int s, int kt) {
        int kg = kSplit + kt * BK;
        #pragma unroll
        for (int r = 0; r < 2; r++) {
            int idx  = tid + r * 256;
            int krow = idx >> 5, c4 = idx & 31;
            cp16(&As[s][krow][c4 * 4], g_A + (size_t)(kg + krow) * BATCH + mBase + c4 * 4);
            cp16(&Ws[s][krow][c4 * 4], g_W + (size_t)(kg + krow) * N     + nBase + c4 * 4);
        }
    };

    float acc[8][8];
    #pragma unroll
    for (int i = 0; i < 8; i++)
        #pragma unroll
        for (int j = 0; j < 8; j++) acc[i][j] = 0.0f;

    loadTiles(0, 0);
    asm volatile("cp.async.commit_group;\n");
    asm volatile("cp.async.wait_group 0;\n");
    __syncthreads();

    for (int kt = 0; kt < ntiles; kt++) {
        const int cur = kt & 1;
        if (kt + 1 < ntiles) loadTiles(cur ^ 1, kt + 1);
        asm volatile("cp.async.commit_group;\n");

        float tAcc[8][8];
        #pragma unroll
        for (int k = 0; k < BK; k++) {
            float a[8], b[8];
            *(float4*)&a[0] = *(const float4*)&As[cur][k][ty * 8];
            *(float4*)&a[4] = *(const float4*)&As[cur][k][ty * 8 + 4];
            *(float4*)&b[0] = *(const float4*)&Ws[cur][k][tx * 8];
            *(float4*)&b[4] = *(const float4*)&Ws[cur][k][tx * 8 + 4];
            if (k == 0) {
                #pragma unroll
                for (int i = 0; i < 8; i++)
                    #pragma unroll
                    for (int j = 0; j < 8; j++) tAcc[i][j] = a[i] * b[j];
            } else {
                #pragma unroll
                for (int i = 0; i < 8; i++)
                    #pragma unroll
                    for (int j = 0; j < 8; j++) tAcc[i][j] += a[i] * b[j];
            }
        }
        #pragma unroll
        for (int i = 0; i < 8; i++)
            #pragma unroll
            for (int j = 0; j < 8; j++) acc[i][j] += tAcc[i][j];

        asm volatile("cp.async.wait_group 0;\n");
        __syncthreads();
    }

    float* P = g_P + (size_t)blockIdx.z * BATCH * N;
    #pragma unroll
    for (int i = 0; i < 8; i++) {
        int row = mBase + ty * 8 + i;
        int col = nBase + tx * 8;
        *(float4*)&P[(size_t)row * N + col]     = *(float4*)&acc[i][0];
        *(float4*)&P[(size_t)row * N + col + 4] = *(float4*)&acc[i][4];
    }
}

// ---------------------------------------------------------------------------
// bf16x6 tensor-core GEMM (layer 2 only): warp tile 32x64, 6 HMMA per
// (mf,nf) per k16; A split in-register from fp32 smem; B planes pre-packed.
// ---------------------------------------------------------------------------
__global__ void __launch_bounds__(256, 1)
gemm_mma_kernel(int K, int N) {
    __shared__ float    As[2][BK][BM + 4];
    __shared__ uint32_t Bs[2][3][BK / 2][BN + 8];

    const int tid  = threadIdx.x;
    const int lane = tid & 31, warp = tid >> 5;
    const int warpM = warp & 3, warpN = warp >> 2;
    const int grp = lane >> 2, tig = lane & 3;

    const int nBase  = blockIdx.x * BN;
    const int mBase  = blockIdx.y * BM;
    const int Kper   = K / SPLITS;
    const int kSplit = blockIdx.z * Kper;
    const int ntiles = Kper / BK;

    auto loadTiles = [&](int s, int kt) {
        const int kg  = kSplit + kt * BK;
        const int kg2 = kg >> 1;
        #pragma unroll
        for (int r = 0; r < 2; r++) {
            int idx = tid + r * 256;
            int krow = idx >> 5, c4 = idx & 31;
            cp16(&As[s][krow][c4 * 4], g_A + (size_t)(kg + krow) * BATCH + mBase + c4 * 4);
        }
        {
            int krow = tid >> 5, c4 = tid & 31;
            size_t gofs = (size_t)(kg2 + krow) * N + nBase + c4 * 4;
            cp16(&Bs[s][0][krow][c4 * 4], g_WH + gofs);
            cp16(&Bs[s][1][krow][c4 * 4], g_WM + gofs);
            cp16(&Bs[s][2][krow][c4 * 4], g_WL + gofs);
        }
    };

    float acc[2][8][4];
    #pragma unroll
    for (int mf = 0; mf < 2; mf++)
        #pragma unroll
        for (int nf = 0; nf < 8; nf++)
            #pragma unroll
            for (int q = 0; q < 4; q++) acc[mf][nf][q] = 0.0f;

    loadTiles(0, 0);
    asm volatile("cp.async.commit_group;\n");
    asm volatile("cp.async.wait_group 0;\n");
    __syncthreads();

    for (int kt = 0; kt < ntiles; kt++) {
        const int cur = kt & 1;
        if (kt + 1 < ntiles) loadTiles(cur ^ 1, kt + 1);
        asm volatile("cp.async.commit_group;\n");

        uint32_t ah[2][4], am[2][4], al[2][4];
        #pragma unroll
        for (int mf = 0; mf < 2; mf++) {
            const int r0 = warpM * 32 + mf * 16 + grp;
            split_pack(As[cur][2*tig    ][r0],     As[cur][2*tig + 1][r0],     ah[mf][0], am[mf][0], al[mf][0]);
            split_pack(As[cur][2*tig    ][r0 + 8], As[cur][2*tig + 1][r0 + 8], ah[mf][1], am[mf][1], al[mf][1]);
            split_pack(As[cur][2*tig + 8][r0],     As[cur][2*tig + 9][r0],     ah[mf][2], am[mf][2], al[mf][2]);
            split_pack(As[cur][2*tig + 8][r0 + 8], As[cur][2*tig + 9][r0 + 8], ah[mf][3], am[mf][3], al[mf][3]);
        }
        #pragma unroll
        for (int nf = 0; nf < 8; nf++) {
            const int c0 = warpN * 64 + nf * 8 + grp;
            uint32_t bh[2] = { Bs[cur][0][tig][c0], Bs[cur][0][tig + 4][c0] };
            uint32_t bm[2] = { Bs[cur][1][tig][c0], Bs[cur][1][tig + 4][c0] };
            uint32_t bl[2] = { Bs[cur][2][tig][c0], Bs[cur][2][tig + 4][c0] };
            #pragma unroll
            for (int mf = 0; mf < 2; mf++) {
                mma_bf16(acc[mf][nf], ah[mf], bh);   // hh
                mma_bf16(acc[mf][nf], ah[mf], bm);   // hm
                mma_bf16(acc[mf][nf], am[mf], bh);   // mh
                mma_bf16(acc[mf][nf], am[mf], bm);   // mm
                mma_bf16(acc[mf][nf], ah[mf], bl);   // hl
                mma_bf16(acc[mf][nf], al[mf], bh);   // lh
            }
        }

        asm volatile("cp.async.wait_group 0;\n");
        __syncthreads();
    }

    float* P = g_P + (size_t)blockIdx.z * BATCH * N;
    #pragma unroll
    for (int mf = 0; mf < 2; mf++) {
        #pragma unroll
        for (int nf = 0; nf < 8; nf++) {
            int row = mBase + warpM * 32 + mf * 16 + grp;
            int col = nBase + warpN * 64 + nf * 8 + tig * 2;
            *(float2*)&P[(size_t)row * N + col]       = make_float2(acc[mf][nf][0], acc[mf][nf][1]);
            *(float2*)&P[(size_t)(row + 8) * N + col] = make_float2(acc[mf][nf][2], acc[mf][nf][3]);
        }
    }
}

// ---------------------------------------------------------------------------
__global__ void reduce_kernel(const float* __restrict__ beta, float* __restrict__ out, int N) {
    const int t = blockIdx.x * blockDim.x + threadIdx.x;
    const int MN = BATCH * N;
    if (t >= MN) return;
    const int o = t % N;
    float acc = beta[o];
    #pragma unroll
    for (int s = 0; s < SPLITS; s++) acc += g_P[(size_t)s * MN + t];
    out[t] = acc;
}

// ---------------------------------------------------------------------------
static void run_layer_ffma(const float* xin, const float* C, const float* alpha,
                           const float* beta, float* xout, int I, int O) {
    const int K = 131 * I;
    wgen_kernel<<<dim3(I, O / 64), 256>>>(C, alpha, I, O);
    agen_kernel<<<(BATCH * I) / 256, 256>>>(xin, I);
    gemm_kernel<<<dim3(O / BN, BATCH / BM, SPLITS), 256>>>(K, O);
    reduce_kernel<<<(BATCH * O + 255) / 256, 256>>>(beta, xout, O);
}

static void run_layer_mma(const float* xin, const float* C, const float* alpha,
                          const float* beta, float* xout, int I, int O) {
    const int K = 131 * I;
    wgen_mma_kernel<<<dim3(I / 2, O / 32), 256>>>(C, alpha, I, O);
    agen_kernel<<<(BATCH * I) / 256, 256>>>(xin, I);
    gemm_mma_kernel<<<dim3(O / BN, BATCH / BM, SPLITS), 256>>>(K, O);
    reduce_kernel<<<(BATCH * O + 255) / 256, 256>>>(beta, xout, O);
}

extern "C" void kernel_launch(void* const* d_in, const int* in_sizes, int n_in,
                              void* d_out, int out_size) {
    const float* x  = (const float*)d_in[0];
    const float* c0 = (const float*)d_in[1];
    const float* a0 = (const float*)d_in[2];
    const float* b0 = (const float*)d_in[3];
    const float* c1 = (const float*)d_in[4];
    const float* a1 = (const float*)d_in[5];
    const float* b1 = (const float*)d_in[6];
    const float* c2 = (const float*)d_in[7];
    const float* a2 = (const float*)d_in[8];
    const float* b2 = (const float*)d_in[9];
    float* out = (float*)d_out;

    float *px0, *px1, *px2;
    cudaGetSymbolAddress((void**)&px0, g_x0);
    cudaGetSymbolAddress((void**)&px1, g_x1);
    cudaGetSymbolAddress((void**)&px2, g_x2);

    tanh_kernel<<<(BATCH * 256) / 256, 256>>>(x, px0, BATCH * 256);

    run_layer_ffma(px0, c0, a0, b0, px1, 256, 512);   // amp ~70: stays fp32
    run_layer_ffma(px1, c1, a1, b1, px2, 512, 512);   // amp ~10: stays fp32
    run_layer_mma (px2, c2, a2, b2, out, 512, 256);   // amp 1: tensor cores
}